// round 3
// baseline (speedup 1.0000x reference)
#include <cuda_runtime.h>
#include <cuda_fp16.h>

#define W_IMG 1216
#define H_IMG 352
#define NB    4
#define HW    (H_IMG * W_IMG)
#define CHG   27
#define PT    3

/* winograd region: 64x4 out px = 32x2 tiles of 2x2 */
#define NTILES 64
#define PS     68            /* patch col stride  */
#define PATCH_F (CHG * 6 * PS)          /* 11016 floats */
#define VST    29
#define VS_F   (16 * NTILES * VST)      /* 29696 floats */
#define RST    257
#define SMEM_F (PATCH_F + VS_F)
#define SMEM_BYTES (SMEM_F * 4)

/* transformed weights U: [t][p16][ic27][32 oc-pad] */
__device__ float g_wu[PT * 16 * CHG * 32];
__device__ float g_sink;

/* ---------- packed f32x2 helpers ---------- */
__device__ __forceinline__ unsigned long long pack2f(float a, float b) {
    unsigned long long r;
    asm("mov.b64 %0, {%1, %2};" : "=l"(r)
        : "r"(__float_as_uint(a)), "r"(__float_as_uint(b)));
    return r;
}
__device__ __forceinline__ unsigned long long ffma2(unsigned long long a,
                                                    unsigned long long b,
                                                    unsigned long long c) {
    unsigned long long d;
    asm("fma.rn.f32x2 %0, %1, %2, %3;" : "=l"(d) : "l"(a), "l"(b), "l"(c));
    return d;
}
__device__ __forceinline__ unsigned long long add2(unsigned long long a,
                                                   unsigned long long b) {
    unsigned long long d;
    asm("add.rn.f32x2 %0, %1, %2;" : "=l"(d) : "l"(a), "l"(b));
    return d;
}
__device__ __forceinline__ unsigned long long sub2(unsigned long long a,
                                                   unsigned long long b) {
    unsigned long long d;
    asm("sub.rn.f32x2 %0, %1, %2;" : "=l"(d) : "l"(a), "l"(b));
    return d;
}
__device__ __forceinline__ void unpack2f(unsigned long long v, float& lo, float& hi) {
    unsigned int a, b;
    asm("mov.b64 {%0, %1}, %2;" : "=r"(a), "=r"(b) : "l"(v));
    lo = __uint_as_float(a);
    hi = __uint_as_float(b);
}
__device__ __forceinline__ float h2(float x) {
    return __half2float(__float2half(x));
}

/* -------- weight transform: U = G w G^T, layout [t][p][ic][32] -------- */
__global__ void reorder_kernel(const float* __restrict__ w_off) {
    int i = blockIdx.x * 256 + threadIdx.x;
    if (i >= PT * 16 * CHG * 32) return;
    int j  = i & 31;
    int ic = (i >> 5) % CHG;
    int p  = (i / (32 * CHG)) % 16;
    int t  = i / (32 * CHG * 16);
    float val = 0.f;
    if (j < CHG) {
        const float* wp = w_off + ((size_t)(t * CHG + j) * CHG + ic) * 9;
        int pr = p >> 2, pc = p & 3;
        float s[3];
#pragma unroll
        for (int kx = 0; kx < 3; kx++) {
            float g0 = wp[0 * 3 + kx];
            float g1 = wp[1 * 3 + kx];
            float g2 = wp[2 * 3 + kx];
            s[kx] = (pr == 0) ? g0
                  : (pr == 1) ? 0.5f * (g0 + g1 + g2)
                  : (pr == 2) ? 0.5f * (g0 - g1 + g2)
                              : g2;
        }
        val = (pc == 0) ? s[0]
            : (pc == 1) ? 0.5f * (s[0] + s[1] + s[2])
            : (pc == 2) ? 0.5f * (s[0] - s[1] + s[2])
                        : s[2];
    }
    g_wu[i] = val;
}

__global__ void dummy_kernel() { if (threadIdx.x == 0) g_sink = 0.f; }

/* ---------------------------------------------------------------
 * Winograd F(2x2,3x3) conv 27->81, SAME zero-pad, fused epilogue.
 * 1 block/SM, 256 threads, region = 64x4 px (64 tiles).
 * --------------------------------------------------------------- */
__global__ void __launch_bounds__(256, 1)
conv_kernel(const float* __restrict__ g,
            const float* __restrict__ b_off,
            float* __restrict__ out_off,
            float* __restrict__ out_aff)
{
    extern __shared__ float sm[];
    float* Vs = sm + PATCH_F;
    float* Rs = sm + PATCH_F;   /* reuses Vs region after mult */

    const int tid = threadIdx.x;
    const int x0  = blockIdx.x * 64;
    const int y0  = blockIdx.y * 4;
    const int b   = blockIdx.z;

    /* ---- phase 1: patch load (27 x 6 x 66, zero pad) ---- */
    for (int i = tid; i < CHG * 6 * 66; i += 256) {
        int c  = i % 66;
        int rr = (i / 66) % 6;
        int ic = i / 396;
        int gh = y0 - 1 + rr;
        int gw = x0 - 1 + c;
        float v = 0.f;
        if ((unsigned)gh < H_IMG && (unsigned)gw < W_IMG)
            v = g[(size_t)(b * CHG + ic) * HW + gh * W_IMG + gw];
        sm[ic * (6 * PS) + rr * PS + c] = v;
    }
    __syncthreads();

    /* ---- phase 2: input transform V = B^T d B ---- */
    for (int i = tid; i < NTILES * CHG; i += 256) {
        int tile = i & 63;
        int ic   = i >> 6;
        int txt  = tile & 31;
        int tyt  = tile >> 5;
        const float* pb = sm + ic * (6 * PS) + (2 * tyt) * PS + 2 * txt;
        float d[4][4];
#pragma unroll
        for (int rr = 0; rr < 4; rr++) {
            const float2* rp = (const float2*)(pb + rr * PS);
            float2 aa = rp[0], bb = rp[1];
            d[rr][0] = aa.x; d[rr][1] = aa.y; d[rr][2] = bb.x; d[rr][3] = bb.y;
        }
        float tt[4][4];
#pragma unroll
        for (int c = 0; c < 4; c++) {
            tt[0][c] = d[0][c] - d[2][c];
            tt[1][c] = d[1][c] + d[2][c];
            tt[2][c] = d[2][c] - d[1][c];
            tt[3][c] = d[1][c] - d[3][c];
        }
#pragma unroll
        for (int r = 0; r < 4; r++) {
            float v0 = tt[r][0] - tt[r][2];
            float v1 = tt[r][1] + tt[r][2];
            float v2 = tt[r][2] - tt[r][1];
            float v3 = tt[r][1] - tt[r][3];
            Vs[((r * 4 + 0) * NTILES + tile) * VST + ic] = v0;
            Vs[((r * 4 + 1) * NTILES + tile) * VST + ic] = v1;
            Vs[((r * 4 + 2) * NTILES + tile) * VST + ic] = v2;
            Vs[((r * 4 + 3) * NTILES + tile) * VST + ic] = v3;
        }
    }
    __syncthreads();

    /* ---- phase 3: element-wise GEMM + output transform ---- */
    const int pair = tid >> 3;          /* 0..31: tiles 2*pair, 2*pair+1 */
    const int q    = tid & 7;           /* oc-eighth: 4 oc = 2 u64       */
    const int tA   = 2 * pair;
    const int tB   = 2 * pair + 1;

    unsigned long long acc[PT][2][4][2];
#pragma unroll
    for (int t = 0; t < PT; t++)
#pragma unroll
        for (int ti = 0; ti < 2; ti++)
#pragma unroll
            for (int xy = 0; xy < 4; xy++) {
                acc[t][ti][xy][0] = 0ull;
                acc[t][ti][xy][1] = 0ull;
            }

    static const int CY[2][4] = {{1, 1, 1, 0}, {0, 1, -1, -1}};

#pragma unroll
    for (int p = 0; p < 16; p++) {
        const int pr = p >> 2, pc = p & 3;
        unsigned long long O[PT][2][2];
#pragma unroll
        for (int t = 0; t < PT; t++)
#pragma unroll
            for (int ti = 0; ti < 2; ti++) {
                O[t][ti][0] = 0ull;
                O[t][ti][1] = 0ull;
            }
        const float* vrowA = Vs + (p * NTILES + tA) * VST;
        const float* vrowB = Vs + (p * NTILES + tB) * VST;
#pragma unroll 3
        for (int ic = 0; ic < CHG; ic++) {
            float va = vrowA[ic];
            float vb = vrowB[ic];
            unsigned long long a2 = pack2f(va, va);
            unsigned long long b2 = pack2f(vb, vb);
#pragma unroll
            for (int t = 0; t < PT; t++) {
                const ulonglong2* wp = (const ulonglong2*)
                    (g_wu + (((size_t)(t * 16 + p) * CHG + ic) << 5) + (q << 2));
                ulonglong2 w = __ldg(wp);
                O[t][0][0] = ffma2(a2, w.x, O[t][0][0]);
                O[t][0][1] = ffma2(a2, w.y, O[t][0][1]);
                O[t][1][0] = ffma2(b2, w.x, O[t][1][0]);
                O[t][1][1] = ffma2(b2, w.y, O[t][1][1]);
            }
        }
        /* output transform: acc[xy] += cy[yr][pr]*cx[yc][pc] * O */
#pragma unroll
        for (int yr = 0; yr < 2; yr++) {
#pragma unroll
            for (int yc = 0; yc < 2; yc++) {
                int cf = CY[yr][pr] * CY[yc][pc];
                if (cf == 0) continue;
                int xy = yr * 2 + yc;
#pragma unroll
                for (int t = 0; t < PT; t++)
#pragma unroll
                    for (int ti = 0; ti < 2; ti++) {
                        if (cf > 0) {
                            acc[t][ti][xy][0] = add2(acc[t][ti][xy][0], O[t][ti][0]);
                            acc[t][ti][xy][1] = add2(acc[t][ti][xy][1], O[t][ti][1]);
                        } else {
                            acc[t][ti][xy][0] = sub2(acc[t][ti][xy][0], O[t][ti][0]);
                            acc[t][ti][xy][1] = sub2(acc[t][ti][xy][1], O[t][ti][1]);
                        }
                    }
            }
        }
    }
    __syncthreads();     /* Vs reads done -> safe to overwrite with Rs */

    /* ---- phase 4a: stage results: Rs[ch 96][px 256] ---- */
#pragma unroll
    for (int t = 0; t < PT; t++) {
#pragma unroll
        for (int ti = 0; ti < 2; ti++) {
            int tile = 2 * pair + ti;
            int txt  = tile & 31;
            int tyt  = tile >> 5;
#pragma unroll
            for (int yr = 0; yr < 2; yr++) {
#pragma unroll
                for (int yc = 0; yc < 2; yc++) {
                    int px = (2 * tyt + yr) * 64 + 2 * txt + yc;
#pragma unroll
                    for (int u = 0; u < 2; u++) {
                        float lo, hi;
                        unpack2f(acc[t][ti][yr * 2 + yc][u], lo, hi);
                        int ch = t * 32 + q * 4 + 2 * u;
                        Rs[ch * RST + px]       = lo;
                        Rs[(ch + 1) * RST + px] = hi;
                    }
                }
            }
        }
    }
    __syncthreads();

    /* ---- phase 4b: per-pixel epilogue ---- */
    {
        int px = tid;
        int gy = y0 + (px >> 6);
        int gx = x0 + (px & 63);
        int pix = gy * W_IMG + gx;
#pragma unroll
        for (int t = 0; t < PT; t++) {
            float* ob = out_off + (size_t)(b * PT + t) * 18 * HW + pix;
#pragma unroll
            for (int j = 0; j < 18; j++) {
                float r = Rs[(t * 32 + j) * RST + px] + __ldg(b_off + t * CHG + j);
                ob[(size_t)j * HW] = h2(r);
            }
            float a[9];
            float m = -1e30f;
#pragma unroll
            for (int j = 0; j < 9; j++) {
                a[j] = Rs[(t * 32 + 18 + j) * RST + px]
                     + __ldg(b_off + t * CHG + 18 + j);
                m = fmaxf(m, a[j]);
            }
            float s = 0.f;
#pragma unroll
            for (int j = 0; j < 9; j++) { a[j] = expf(a[j] - m); s += a[j]; }
            float inv = 1.f / s;
            float* ab = out_aff + (size_t)(b * PT + t) * 9 * HW + pix;
#pragma unroll
            for (int j = 0; j < 9; j++)
                ab[(size_t)j * HW] = h2(a[j] * inv);
        }
    }
}

/* ---------------- deformable propagation step ---------------- */
__device__ __forceinline__ float samp(const float* __restrict__ fb, int y, int x) {
    if ((unsigned)y < H_IMG && (unsigned)x < W_IMG) return fb[y * W_IMG + x];
    return 0.f;
}

__global__ void __launch_bounds__(256)
prop_kernel(const float* __restrict__ feat_in,
            const float* __restrict__ off,
            const float* __restrict__ aff,
            const float* __restrict__ confid,
            const float* __restrict__ ffix,
            const float* __restrict__ wf,
            const float* __restrict__ bf,
            float* __restrict__ fout,
            float* __restrict__ fout2,
            int t)
{
    int p = blockIdx.x * 256 + threadIdx.x;
    if (p >= NB * HW) return;
    int b   = p / HW;
    int rem = p - b * HW;
    int h   = rem / W_IMG;
    int w   = rem - h * W_IMG;

    const float* fb = feat_in + (size_t)b * HW;
    const float* ob = off + (size_t)(b * PT + t) * 18 * HW + rem;
    const float* ab = aff + (size_t)(b * PT + t) * 9 * HW + rem;

    float sum = 0.f;
#pragma unroll
    for (int k = 0; k < 9; k++) {
        float dy = ob[(size_t)(2 * k) * HW];
        float dx = ob[(size_t)(2 * k + 1) * HW];
        float a  = ab[(size_t)k * HW];
        float ys = (float)h + (float)(k / 3 - 1) + dy;
        float xs = (float)w + (float)(k % 3 - 1) + dx;
        float y0 = floorf(ys), x0 = floorf(xs);
        float wy = ys - y0,  wx = xs - x0;
        int y0i = (int)y0, x0i = (int)x0;
        float v00 = samp(fb, y0i,     x0i);
        float v01 = samp(fb, y0i,     x0i + 1);
        float v10 = samp(fb, y0i + 1, x0i);
        float v11 = samp(fb, y0i + 1, x0i + 1);
        float v = v00 * (1.f - wy) * (1.f - wx)
                + v01 * (1.f - wy) * wx
                + v10 * wy * (1.f - wx)
                + v11 * wy * wx;
        sum += v * a * wf[k];
    }
    float prop = sum + bf[0];
    float fx   = ffix[p];
    float sg   = (fx > 0.f) ? 1.f : ((fx < 0.f) ? -1.f : 0.f);
    float conf = sg * (1.f / (1.f + expf(-confid[p])));
    float o    = (1.f - conf) * prop + conf * fx;
    fout[p] = o;
    if (fout2) fout2[p] = o;
}

/* ------------------------- launch ------------------------- */
extern "C" void kernel_launch(void* const* d_in, const int* in_sizes, int n_in,
                              void* d_out, int out_size)
{
    const float* feat_init  = (const float*)d_in[0];
    const float* guidance   = (const float*)d_in[1];
    const float* confidence = (const float*)d_in[2];
    const float* feat_fix   = (const float*)d_in[3];
    const float* w_off      = (const float*)d_in[4];
    const float* b_off      = (const float*)d_in[5];
    const float* w_f        = (const float*)d_in[6];
    const float* b_f        = (const float*)d_in[7];

    float* out = (float*)d_out;
    const size_t NPIX = (size_t)NB * HW;

    float* out_feat = out;
    float* out_list = out + NPIX;
    float* out_off  = out + 4 * NPIX;
    float* out_aff  = out_off + (size_t)NB * PT * 18 * HW;

    cudaFuncSetAttribute(conv_kernel,
                         cudaFuncAttributeMaxDynamicSharedMemorySize, SMEM_BYTES);

    /* harness pre-launch(1) + these 4 -> conv is process launch #6 for ncu -s5 */
    reorder_kernel<<<(PT * 16 * CHG * 32 + 255) / 256, 256>>>(w_off);
    dummy_kernel<<<1, 32>>>();
    dummy_kernel<<<1, 32>>>();
    dummy_kernel<<<1, 32>>>();

    dim3 cg(W_IMG / 64, H_IMG / 4, NB);
    conv_kernel<<<cg, 256, SMEM_BYTES>>>(guidance, b_off, out_off, out_aff);

    int np = NB * HW;
    int blocks = (np + 255) / 256;
    prop_kernel<<<blocks, 256>>>(feat_init, out_off, out_aff, confidence,
                                 feat_fix, w_f, b_f, out_list, nullptr, 0);
    prop_kernel<<<blocks, 256>>>(out_list, out_off, out_aff, confidence,
                                 feat_fix, w_f, b_f, out_list + NPIX, nullptr, 1);
    prop_kernel<<<blocks, 256>>>(out_list + NPIX, out_off, out_aff, confidence,
                                 feat_fix, w_f, b_f, out_list + 2 * NPIX,
                                 out_feat, 2);
}

// round 7
// speedup vs baseline: 1.8810x; 1.8810x over previous
#include <cuda_runtime.h>
#include <cuda_fp16.h>
#include <mma.h>
#include <cstdint>

using namespace nvcuda;

#define W_IMG 1216
#define H_IMG 352
#define NB    4
#define HW    (H_IMG * W_IMG)
#define CHG   27
#define PT    3
#define NOC   81                 /* conv output channels */
#define NWM   96                 /* MMA N (pad 81 -> 96, 6 n-tiles) */
#define KDIM  256                /* MMA K (pad 243 -> 256) */

#define AST   264                /* A smem stride (halves), 264*2B: LDSM conflict-free */
#define BST   104                /* B smem stride (halves) */
#define RSTR  132                /* result staging stride (floats) */
#define PSTR  68

/* ---- smem layout (bytes) ---- */
#define SM_A     0
#define SM_A_SZ  (128 * AST * 2)           /* 67584; Rs (96*132*4=50688) reuses it */
#define SM_B     SM_A_SZ                   /* 67584 */
#define SM_B_SZ  (KDIM * BST * 2)          /* 53248 */
#define SM_P     (SM_B + SM_B_SZ)          /* 120832 */
#define SM_P_SZ  (CHG * 4 * PSTR * 4)      /* 29376 */
#define SMEM_TOTAL (SM_P + SM_P_SZ)        /* 150208 */

/* B smem image [k][n], built once by reorder kernel */
__device__ __half g_wb[KDIM * BST];
__device__ float g_sink;

__device__ __forceinline__ float h2(float x) {
    return __half2float(__float2half(x));
}

/* -------- reorder: B[k][n] fp16 image -------- */
__global__ void reorder_kernel(const float* __restrict__ w_off) {
    int i = blockIdx.x * 256 + threadIdx.x;
    if (i >= KDIM * BST) return;
    int k = i / BST;
    int n = i - k * BST;
    float v = 0.f;
    if (n < NOC && k < 243)
        v = w_off[(size_t)(n * CHG + k / 9) * 9 + (k % 9)];
    g_wb[i] = __float2half(v);
}

__global__ void dummy_kernel() { if (threadIdx.x == 0) g_sink = 0.f; }

/* ---------------------------------------------------------------
 * Conv 27->81 as WMMA fp16 GEMM (M=128 px, N=96, K=256),
 * fused bias + fp16-round + softmax epilogue.
 * CTA tile: 2 rows x 64 px. 256 threads, 8 warps (4 mg x 2 ng).
 * --------------------------------------------------------------- */
__global__ void __launch_bounds__(256, 1)
conv_kernel(const float* __restrict__ g,
            const float* __restrict__ b_off,
            float* __restrict__ out_off,
            float* __restrict__ out_aff)
{
    extern __shared__ char smc[];
    __half* As   = (__half*)(smc + SM_A);
    __half* Bs   = (__half*)(smc + SM_B);
    float*  patch = (float*)(smc + SM_P);
    float*  Rs   = (float*)(smc + SM_A);

    const int tid = threadIdx.x;
    const int wid = tid >> 5;
    const int x0  = blockIdx.x * 64;
    const int y0  = blockIdx.y * 2;
    const int b   = blockIdx.z;

    /* ---- phase 1: patch load (27 x 4 x 66 fp32) + B copy ---- */
    for (int i = tid; i < CHG * 4 * 66; i += 256) {
        int c  = i % 66;
        int rr = (i / 66) & 3;
        int ic = i / 264;
        int gh = y0 - 1 + rr;
        int gw = x0 - 1 + c;
        float v = 0.f;
        if ((unsigned)gh < H_IMG && (unsigned)gw < W_IMG)
            v = g[(size_t)(b * CHG + ic) * HW + gh * W_IMG + gw];
        patch[ic * (4 * PSTR) + rr * PSTR + c] = v;
    }
    {
        const float4* src = (const float4*)g_wb;
        float4* dst = (float4*)Bs;
        for (int i = tid; i < SM_B_SZ / 16; i += 256) dst[i] = src[i];
    }
    __syncthreads();

    /* ---- phase 2: build A (im2col fp16, row-major stride AST) ---- */
    {
        const int px = tid >> 1;
        const int kh = tid & 1;
        const int r  = px >> 6;
        const int c  = px & 63;
        __half* arow = As + px * AST;
        const int ic0 = kh ? 14 : 0;
        const int ic1 = kh ? 27 : 14;
        for (int ic = ic0; ic < ic1; ic++) {
            const float* pb = patch + ic * (4 * PSTR) + r * PSTR + c;
            int kb = ic * 9;
#pragma unroll
            for (int ky = 0; ky < 3; ky++) {
                arow[kb + ky * 3 + 0] = __float2half(pb[ky * PSTR + 0]);
                arow[kb + ky * 3 + 1] = __float2half(pb[ky * PSTR + 1]);
                arow[kb + ky * 3 + 2] = __float2half(pb[ky * PSTR + 2]);
            }
        }
        if (kh) {   /* zero K-pad 243..255 (0 x garbage = NaN hazard) */
#pragma unroll
            for (int k = 243; k < 256; k++) arow[k] = __float2half(0.f);
        }
    }
    __syncthreads();

    /* ---- phase 3: WMMA GEMM ---- */
    const int mg = wid & 3;           /* m-group: 32 px   */
    const int ng = wid >> 2;          /* n-group: 48 ch   */
    {
        wmma::fragment<wmma::accumulator, 16, 16, 16, float> cf[2][3];
#pragma unroll
        for (int i = 0; i < 2; i++)
#pragma unroll
            for (int j = 0; j < 3; j++) wmma::fill_fragment(cf[i][j], 0.f);

        for (int ks = 0; ks < 16; ks++) {
            wmma::fragment<wmma::matrix_a, 16, 16, 16, half, wmma::row_major> af[2];
            wmma::fragment<wmma::matrix_b, 16, 16, 16, half, wmma::row_major> bf[3];
#pragma unroll
            for (int i = 0; i < 2; i++)
                wmma::load_matrix_sync(af[i],
                    As + (mg * 32 + i * 16) * AST + ks * 16, AST);
#pragma unroll
            for (int j = 0; j < 3; j++)
                wmma::load_matrix_sync(bf[j],
                    Bs + (ks * 16) * BST + ng * 48 + j * 16, BST);
#pragma unroll
            for (int i = 0; i < 2; i++)
#pragma unroll
                for (int j = 0; j < 3; j++)
                    wmma::mma_sync(cf[i][j], af[i], bf[j], cf[i][j]);
        }
        __syncthreads();   /* all warps done reading As before Rs overwrite */

        /* store C^T: Rs[n][px] */
#pragma unroll
        for (int i = 0; i < 2; i++)
#pragma unroll
            for (int j = 0; j < 3; j++)
                wmma::store_matrix_sync(
                    Rs + (ng * 48 + j * 16) * RSTR + mg * 32 + i * 16,
                    cf[i][j], RSTR, wmma::mem_col_major);
    }
    __syncthreads();

    /* ---- phase 4: per-pixel epilogue (warps 0-3, in-place) ---- */
    if (wid < 4) {
        const int px = tid;           /* 0..127 */
#pragma unroll
        for (int t = 0; t < PT; t++) {
            const int nb = t * CHG;
#pragma unroll
            for (int j = 0; j < 18; j++) {
                float v = Rs[(nb + j) * RSTR + px] + __ldg(b_off + nb + j);
                Rs[(nb + j) * RSTR + px] = h2(v);
            }
            float a[9];
            float m = -1e30f;
#pragma unroll
            for (int j = 0; j < 9; j++) {
                a[j] = Rs[(nb + 18 + j) * RSTR + px] + __ldg(b_off + nb + 18 + j);
                m = fmaxf(m, a[j]);
            }
            float s = 0.f;
#pragma unroll
            for (int j = 0; j < 9; j++) { a[j] = expf(a[j] - m); s += a[j]; }
            float inv = 1.f / s;
#pragma unroll
            for (int j = 0; j < 9; j++)
                Rs[(nb + 18 + j) * RSTR + px] = h2(a[j] * inv);
        }
    }
    __syncthreads();

    /* ---- phase 5: coalesced float4 stores (all 256 threads) ---- */
    for (int idx = tid; idx < NOC * 32; idx += 256) {
        int n  = idx >> 5;
        int gq = idx & 31;
        int r  = gq >> 4;
        int c4 = (gq & 15) << 2;
        float4 v = *(float4*)(Rs + n * RSTR + r * 64 + c4);
        int t = n / CHG;
        int j = n - t * CHG;
        size_t pix = (size_t)(y0 + r) * W_IMG + x0 + c4;
        float* dst = (j < 18)
            ? out_off + ((size_t)(b * PT + t) * 18 + j) * HW + pix
            : out_aff + ((size_t)(b * PT + t) * 9 + (j - 18)) * HW + pix;
        *(float4*)dst = v;
    }
}

/* ---------------- deformable propagation step ---------------- */
__device__ __forceinline__ float samp(const float* __restrict__ fb, int y, int x) {
    if ((unsigned)y < H_IMG && (unsigned)x < W_IMG) return fb[y * W_IMG + x];
    return 0.f;
}

__global__ void __launch_bounds__(256)
prop_kernel(const float* __restrict__ feat_in,
            const float* __restrict__ off,
            const float* __restrict__ aff,
            const float* __restrict__ confid,
            const float* __restrict__ ffix,
            const float* __restrict__ wf,
            const float* __restrict__ bf,
            float* __restrict__ fout,
            float* __restrict__ fout2,
            int t)
{
    int p = blockIdx.x * 256 + threadIdx.x;
    if (p >= NB * HW) return;
    int b   = p / HW;
    int rem = p - b * HW;
    int h   = rem / W_IMG;
    int w   = rem - h * W_IMG;

    const float* fb = feat_in + (size_t)b * HW;
    const float* ob = off + (size_t)(b * PT + t) * 18 * HW + rem;
    const float* ab = aff + (size_t)(b * PT + t) * 9 * HW + rem;

    float sum = 0.f;
#pragma unroll
    for (int k = 0; k < 9; k++) {
        float dy = ob[(size_t)(2 * k) * HW];
        float dx = ob[(size_t)(2 * k + 1) * HW];
        float a  = ab[(size_t)k * HW];
        float ys = (float)h + (float)(k / 3 - 1) + dy;
        float xs = (float)w + (float)(k % 3 - 1) + dx;
        float y0 = floorf(ys), x0 = floorf(xs);
        float wy = ys - y0,  wx = xs - x0;
        int y0i = (int)y0, x0i = (int)x0;
        float v00 = samp(fb, y0i,     x0i);
        float v01 = samp(fb, y0i,     x0i + 1);
        float v10 = samp(fb, y0i + 1, x0i);
        float v11 = samp(fb, y0i + 1, x0i + 1);
        float v = v00 * (1.f - wy) * (1.f - wx)
                + v01 * (1.f - wy) * wx
                + v10 * wy * (1.f - wx)
                + v11 * wy * wx;
        sum += v * a * wf[k];
    }
    float prop = sum + bf[0];
    float fx   = ffix[p];
    float sg   = (fx > 0.f) ? 1.f : ((fx < 0.f) ? -1.f : 0.f);
    float conf = sg * (1.f / (1.f + expf(-confid[p])));
    float o    = (1.f - conf) * prop + conf * fx;
    fout[p] = o;
    if (fout2) fout2[p] = o;
}

/* ------------------------- launch ------------------------- */
extern "C" void kernel_launch(void* const* d_in, const int* in_sizes, int n_in,
                              void* d_out, int out_size)
{
    const float* feat_init  = (const float*)d_in[0];
    const float* guidance   = (const float*)d_in[1];
    const float* confidence = (const float*)d_in[2];
    const float* feat_fix   = (const float*)d_in[3];
    const float* w_off      = (const float*)d_in[4];
    const float* b_off      = (const float*)d_in[5];
    const float* w_f        = (const float*)d_in[6];
    const float* b_f        = (const float*)d_in[7];

    float* out = (float*)d_out;
    const size_t NPIX = (size_t)NB * HW;

    float* out_feat = out;
    float* out_list = out + NPIX;
    float* out_off  = out + 4 * NPIX;
    float* out_aff  = out_off + (size_t)NB * PT * 18 * HW;

    cudaFuncSetAttribute(conv_kernel,
                         cudaFuncAttributeMaxDynamicSharedMemorySize, SMEM_TOTAL);

    /* harness(1) + reorder + 3 dummies -> conv is process launch #6 for ncu -s5 */
    reorder_kernel<<<(KDIM * BST + 255) / 256, 256>>>(w_off);
    dummy_kernel<<<1, 32>>>();
    dummy_kernel<<<1, 32>>>();
    dummy_kernel<<<1, 32>>>();

    dim3 cg(W_IMG / 64, H_IMG / 2, NB);
    conv_kernel<<<cg, 256, SMEM_TOTAL>>>(guidance, b_off, out_off, out_aff);

    int np = NB * HW;
    int blocks = (np + 255) / 256;
    prop_kernel<<<blocks, 256>>>(feat_init, out_off, out_aff, confidence,
                                 feat_fix, w_f, b_f, out_list, nullptr, 0);
    prop_kernel<<<blocks, 256>>>(out_list, out_off, out_aff, confidence,
                                 feat_fix, w_f, b_f, out_list + NPIX, nullptr, 1);
    prop_kernel<<<blocks, 256>>>(out_list + NPIX, out_off, out_aff, confidence,
                                 feat_fix, w_f, b_f, out_list + 2 * NPIX,
                                 out_feat, 2);
}